// round 4
// baseline (speedup 1.0000x reference)
#include <cuda_runtime.h>
#include <stdint.h>

// Scratch (allocation-free per harness rules). Zero-initialized at load;
// last block resets both after use so every graph replay starts clean.
__device__ float        g_acc;
__device__ unsigned int g_count;

#define THREADS      256
#define TILE_ROWS    512                   // 512 rows * 14 f32 = 28672 B
#define TILE_FLOATS  (TILE_ROWS * 14)      // 7168
#define TILE_UINT4   (TILE_FLOATS / 4)     // 1792 = 7 * THREADS

__global__ void __launch_bounds__(THREADS)
hcl_fused_kernel(const float* __restrict__ pred,
                 const float* __restrict__ temp,
                 const int*   __restrict__ i_idx,
                 const int*   __restrict__ j_idx,
                 float*       __restrict__ out,
                 long long rows, int num_constraints, int vec16)
{
    const int i0 = __ldg(i_idx + 0), i1 = __ldg(i_idx + 1),
              i2 = __ldg(i_idx + 2), i3 = __ldg(i_idx + 3);
    const int j0 = __ldg(j_idx + 0), j1 = __ldg(j_idx + 1),
              j2 = __ldg(j_idx + 2), j3 = __ldg(j_idx + 3);

    // Specialized path for the dataset's fixed constraint set:
    // pairs (2,5),(5,6),(6,7),(8,3) -> unique cols {2,3,5,6,7,8}.
    const bool fast = (num_constraints == 4 &&
                       i0 == 2 && i1 == 5 && i2 == 6 && i3 == 8 &&
                       j0 == 5 && j1 == 6 && j2 == 7 && j3 == 3);

    float acc = 0.0f;
    const int tid = threadIdx.x;

    if (fast) {
        __shared__ __align__(16) float s[TILE_FLOATS];

        const long long nTiles      = (rows + TILE_ROWS - 1) / TILE_ROWS;
        const long long totalFloats = rows * 14;

        for (long long tile = blockIdx.x; tile < nTiles; tile += gridDim.x) {
            const long long baseF   = tile * (long long)TILE_FLOATS;
            const long long baseRow = tile * TILE_ROWS;
            const int rowsInTile =
                (int)((rows - baseRow) < TILE_ROWS ? (rows - baseRow) : TILE_ROWS);

            if (vec16) {
                // 16B-aligned global: ideal LDG.128 streaming
                uint4* s4 = reinterpret_cast<uint4*>(s);
                const uint4* p4 = reinterpret_cast<const uint4*>(pred);
                const long long total4 = totalFloats >> 2;
                const long long base4  = baseF >> 2;
                #pragma unroll
                for (int k = 0; k < 7; k++) {
                    int s_idx = tid + k * THREADS;
                    long long g = base4 + s_idx;
                    if (g < total4) s4[s_idx] = p4[g];
                }
            } else {
                // Alignment-safe: coalesced scalar loads (same wavefronts/warp)
                #pragma unroll
                for (int k = 0; k < 28; k++) {
                    int s_idx = tid + k * THREADS;
                    long long g = baseF + s_idx;
                    if (g < totalFloats) s[s_idx] = __ldg(pred + g);
                }
            }
            __syncthreads();

            // Each thread consumes 2 rows from smem
            #pragma unroll
            for (int rr = 0; rr < 2; rr++) {
                int r = 2 * tid + rr;
                if (r < rowsInTile) {
                    const float* row = s + r * 14;
                    float p2 = row[2], p3 = row[3];
                    float p5 = row[5];
                    float p6 = row[6], p7 = row[7];
                    float p8 = row[8];

                    float d0 = fmaxf(p2 - p5, 0.0f);
                    float d1 = fmaxf(p5 - p6, 0.0f);
                    float d2 = fmaxf(p6 - p7, 0.0f);
                    float d3 = fmaxf(p8 - p3, 0.0f);

                    acc = fmaf(d0, d0, acc);
                    acc = fmaf(d1, d1, acc);
                    acc = fmaf(d2, d2, acc);
                    acc = fmaf(d3, d3, acc);
                }
            }
            __syncthreads();
        }
    } else {
        // Generic fallback: direct scalar gather (correct for any indices)
        long long t      = (long long)blockIdx.x * blockDim.x + threadIdx.x;
        long long stride = (long long)gridDim.x * blockDim.x;
        for (long long r = t; r < rows; r += stride) {
            const float* row = pred + r * 14;
            float a0 = __ldg(row + i0), b0 = __ldg(row + j0);
            float a1 = __ldg(row + i1), b1 = __ldg(row + j1);
            float a2 = __ldg(row + i2), b2 = __ldg(row + j2);
            float a3 = __ldg(row + i3), b3 = __ldg(row + j3);
            float d0 = fmaxf(a0 - b0, 0.0f);
            float d1 = fmaxf(a1 - b1, 0.0f);
            float d2 = fmaxf(a2 - b2, 0.0f);
            float d3 = fmaxf(a3 - b3, 0.0f);
            acc = fmaf(d0, d0, acc);
            acc = fmaf(d1, d1, acc);
            acc = fmaf(d2, d2, acc);
            acc = fmaf(d3, d3, acc);
        }
    }

    // Warp reduction
    #pragma unroll
    for (int off = 16; off > 0; off >>= 1)
        acc += __shfl_xor_sync(0xFFFFFFFFu, acc, off);

    // Block reduction -> one global atomic per block
    __shared__ float s_part;
    __shared__ bool  s_last;
    if (threadIdx.x == 0) s_part = 0.0f;
    __syncthreads();
    if ((threadIdx.x & 31) == 0) atomicAdd(&s_part, acc);
    __syncthreads();

    if (threadIdx.x == 0) {
        atomicAdd(&g_acc, s_part);
        __threadfence();
        unsigned c = atomicAdd(&g_count, 1u);
        s_last = (c == (unsigned)gridDim.x - 1u);
    }
    __syncthreads();

    // Last block finalizes: read+reset accumulator, write output, reset counter.
    if (s_last && threadIdx.x == 0) {
        float total = atomicExch(&g_acc, 0.0f);
        out[0] = total / ((float)rows * temp[0] * (float)num_constraints);
        g_count = 0u;
    }
}

extern "C" void kernel_launch(void* const* d_in, const int* in_sizes, int n_in,
                              void* d_out, int out_size)
{
    const float* pred  = (const float*)d_in[0];
    const float* temp  = (const float*)d_in[1];
    const int*   i_idx = (const int*)d_in[2];
    const int*   j_idx = (const int*)d_in[3];
    float* out = (float*)d_out;

    const int num_classes = 14;                       // fixed problem shape
    const long long rows = (long long)in_sizes[0] / num_classes;
    const int num_constraints = in_sizes[2];          // 4

    const int vec16 = (((uintptr_t)pred & 15) == 0) ? 1 : 0;

    const long long nTiles = (rows + TILE_ROWS - 1) / TILE_ROWS;
    int blocks = (int)(nTiles < 1184 ? nTiles : 1184); // 148 SMs * 8 (28KB smem/block)

    hcl_fused_kernel<<<blocks, THREADS>>>(pred, temp, i_idx, j_idx, out,
                                          rows, num_constraints, vec16);
}

// round 5
// speedup vs baseline: 1.9317x; 1.9317x over previous
#include <cuda_runtime.h>
#include <stdint.h>

// Scratch (allocation-free per harness rules). Zero-initialized at load;
// last block resets both after use so every graph replay starts clean.
__device__ float        g_acc;
__device__ unsigned int g_count;

#define THREADS    128
#define TILE_U4    896                 // float4 per tile = 7 * THREADS
#define TILE_ROWS  256                 // 896*4/14
#define NBUF_U4    (2 * TILE_U4)       // double buffer: 28672 B

__global__ void __launch_bounds__(THREADS)
hcl_fused_kernel(const float* __restrict__ pred,
                 const float* __restrict__ temp,
                 const int*   __restrict__ i_idx,
                 const int*   __restrict__ j_idx,
                 float*       __restrict__ out,
                 long long rows, int num_constraints, int vec16)
{
    const int i0 = __ldg(i_idx + 0), i1 = __ldg(i_idx + 1),
              i2 = __ldg(i_idx + 2), i3 = __ldg(i_idx + 3);
    const int j0 = __ldg(j_idx + 0), j1 = __ldg(j_idx + 1),
              j2 = __ldg(j_idx + 2), j3 = __ldg(j_idx + 3);

    // Specialized path: dataset's fixed constraints (2,5),(5,6),(6,7),(8,3),
    // 16B-aligned input, even row count.
    const bool fast = (num_constraints == 4 && vec16 && (rows & 1) == 0 &&
                       i0 == 2 && i1 == 5 && i2 == 6 && i3 == 8 &&
                       j0 == 5 && j1 == 6 && j2 == 7 && j3 == 3);

    float acc = 0.0f;
    const int tid = threadIdx.x;

    if (fast) {
        __shared__ __align__(16) float4 sbuf[NBUF_U4];

        const long long total4 = rows * 14 / 4;                 // exact (rows even)
        const long long nTiles = (total4 + TILE_U4 - 1) / TILE_U4;
        const float4* p4 = reinterpret_cast<const float4*>(pred);

        // Stage a tile into buffer b via cp.async (global -> smem, L1 bypass)
        auto stage = [&](int b, long long tile) {
            const long long base4 = tile * (long long)TILE_U4;
            #pragma unroll
            for (int k = 0; k < 7; k++) {
                int s_idx = tid + k * THREADS;
                long long g = base4 + s_idx;
                if (g < total4) {
                    unsigned dst = (unsigned)__cvta_generic_to_shared(
                        &sbuf[b * TILE_U4 + s_idx]);
                    asm volatile(
                        "cp.async.cg.shared.global [%0], [%1], 16;\n"
                        :: "r"(dst), "l"(p4 + g) : "memory");
                }
            }
            asm volatile("cp.async.commit_group;\n" ::: "memory");
        };

        long long tile = blockIdx.x;
        int buf = 0;
        if (tile < nTiles) stage(0, tile);

        for (; tile < nTiles; tile += gridDim.x) {
            const long long next = tile + gridDim.x;
            if (next < nTiles) {
                stage(buf ^ 1, next);
                asm volatile("cp.async.wait_group 1;\n" ::: "memory");
            } else {
                asm volatile("cp.async.wait_group 0;\n" ::: "memory");
            }
            __syncthreads();

            // Consume: thread t owns row pair t (rows 2t, 2t+1 of the tile).
            // float4 index 7t+k -> (7l+k) mod 8 is a permutation within each
            // quarter-warp => conflict-free LDS.128. Only k in {0,1,2,4,5}
            // carry needed columns.
            const long long baseRow = tile * (long long)TILE_ROWS;
            const int rowsInTile =
                (int)((rows - baseRow) < TILE_ROWS ? (rows - baseRow) : TILE_ROWS);
            const int pairsInTile = rowsInTile >> 1;

            if (tid < pairsInTile) {
                const float4* b4 = sbuf + buf * TILE_U4 + 7 * tid;
                float4 u0 = b4[0];   // f0..f3   (row0: c0..c3)
                float4 u1 = b4[1];   // f4..f7   (row0: c4..c7)
                float4 u2 = b4[2];   // f8..f11  (row0: c8..c11)
                float4 u4 = b4[4];   // f16..f19 (row1: c2,c3,c4,c5)
                float4 u5 = b4[5];   // f20..f23 (row1: c6,c7,c8,c9)

                // row 0: p2=u0.z p3=u0.w p5=u1.y p6=u1.z p7=u1.w p8=u2.x
                float d0 = fmaxf(u0.z - u1.y, 0.0f);
                float d1 = fmaxf(u1.y - u1.z, 0.0f);
                float d2 = fmaxf(u1.z - u1.w, 0.0f);
                float d3 = fmaxf(u2.x - u0.w, 0.0f);
                // row 1: p2=u4.x p3=u4.y p5=u4.w p6=u5.x p7=u5.y p8=u5.z
                float e0 = fmaxf(u4.x - u4.w, 0.0f);
                float e1 = fmaxf(u4.w - u5.x, 0.0f);
                float e2 = fmaxf(u5.x - u5.y, 0.0f);
                float e3 = fmaxf(u5.z - u4.y, 0.0f);

                acc = fmaf(d0, d0, acc);
                acc = fmaf(d1, d1, acc);
                acc = fmaf(d2, d2, acc);
                acc = fmaf(d3, d3, acc);
                acc = fmaf(e0, e0, acc);
                acc = fmaf(e1, e1, acc);
                acc = fmaf(e2, e2, acc);
                acc = fmaf(e3, e3, acc);
            }
            __syncthreads();   // all consumed before this buffer is restaged
            buf ^= 1;
        }
    } else {
        // Generic fallback: direct scalar gather (correct for any indices)
        long long t      = (long long)blockIdx.x * blockDim.x + threadIdx.x;
        long long stride = (long long)gridDim.x * blockDim.x;
        for (long long r = t; r < rows; r += stride) {
            const float* row = pred + r * 14;
            float a0 = __ldg(row + i0), b0 = __ldg(row + j0);
            float a1 = __ldg(row + i1), b1 = __ldg(row + j1);
            float a2 = __ldg(row + i2), b2 = __ldg(row + j2);
            float a3 = __ldg(row + i3), b3 = __ldg(row + j3);
            float d0 = fmaxf(a0 - b0, 0.0f);
            float d1 = fmaxf(a1 - b1, 0.0f);
            float d2 = fmaxf(a2 - b2, 0.0f);
            float d3 = fmaxf(a3 - b3, 0.0f);
            acc = fmaf(d0, d0, acc);
            acc = fmaf(d1, d1, acc);
            acc = fmaf(d2, d2, acc);
            acc = fmaf(d3, d3, acc);
        }
    }

    // Warp reduction
    #pragma unroll
    for (int off = 16; off > 0; off >>= 1)
        acc += __shfl_xor_sync(0xFFFFFFFFu, acc, off);

    // Block reduction -> one global atomic per block
    __shared__ float s_part;
    __shared__ bool  s_last;
    if (threadIdx.x == 0) s_part = 0.0f;
    __syncthreads();
    if ((threadIdx.x & 31) == 0) atomicAdd(&s_part, acc);
    __syncthreads();

    if (threadIdx.x == 0) {
        atomicAdd(&g_acc, s_part);
        __threadfence();
        unsigned c = atomicAdd(&g_count, 1u);
        s_last = (c == (unsigned)gridDim.x - 1u);
    }
    __syncthreads();

    // Last block finalizes: read+reset accumulator, write output, reset counter.
    if (s_last && threadIdx.x == 0) {
        float total = atomicExch(&g_acc, 0.0f);
        out[0] = total / ((float)rows * temp[0] * (float)num_constraints);
        g_count = 0u;
    }
}

extern "C" void kernel_launch(void* const* d_in, const int* in_sizes, int n_in,
                              void* d_out, int out_size)
{
    const float* pred  = (const float*)d_in[0];
    const float* temp  = (const float*)d_in[1];
    const int*   i_idx = (const int*)d_in[2];
    const int*   j_idx = (const int*)d_in[3];
    float* out = (float*)d_out;

    const int num_classes = 14;                       // fixed problem shape
    const long long rows = (long long)in_sizes[0] / num_classes;
    const int num_constraints = in_sizes[2];          // 4

    const int vec16 = (((uintptr_t)pred & 15) == 0) ? 1 : 0;

    const long long total4 = rows * 14 / 4;
    const long long nTiles = (total4 + TILE_U4 - 1) / TILE_U4;
    long long want = nTiles < 1036 ? nTiles : 1036;   // 148 SMs * 7 (28KB smem)
    int blocks = (int)(want > 0 ? want : 1);

    hcl_fused_kernel<<<blocks, THREADS>>>(pred, temp, i_idx, j_idx, out,
                                          rows, num_constraints, vec16);
}